// round 5
// baseline (speedup 1.0000x reference)
#include <cuda_runtime.h>
#include <stdint.h>

#define D 256
#define BQ 1024
#define KTOP 1024
#define MMAX 100000
#define CAND_MAX 4096
#define FEAT_BLOCKS 128
#define NBINS (1 << 20)   // 20-bit single-level radix select
#define NCHUNK 1024
#define TROWS 32          // rows per score tile
#define TILE_BYTES (TROWS * D * 4)          // 32 KB
#define SMEM_SCORES (2 * TROWS * D + D)     // floats: 2 tiles + fsum
#define SCORE_BLOCKS 444                     // 3 per SM * 148

// ---------------- static device scratch ----------------
__device__ float g_pfsum[FEAT_BLOCKS][D];
__device__ float g_fsum[D];
__device__ unsigned long long g_keys[MMAX];
__device__ int g_hist[NBINS];          // 4 MB
__device__ int g_chunk[NCHUNK];
__device__ int g_Tbin;
__device__ unsigned long long g_cand[CAND_MAX];
__device__ int g_ncand;
__device__ int g_topidx[KTOP];

// ---------------- K0: fused zero-hist + feature partial sums ----------------
__global__ void k_init(const float* __restrict__ f) {
    int blk = blockIdx.x;
    int t = threadIdx.x;  // 256
    if (blk < FEAT_BLOCKS) {
        const int RPB = BQ / FEAT_BLOCKS;  // 8 rows per block
        float s = 0.f;
        int base = blk * RPB * D + t;
#pragma unroll
        for (int r = 0; r < RPB; r++) s += f[base + r * D];
        g_pfsum[blk][t] = s;
        if (blk == 0 && t == 0) g_ncand = 0;
    } else {
        int c = blk - FEAT_BLOCKS;        // 1024 blocks, 1024 ints each
        ((int4*)g_hist)[c * 256 + t] = make_int4(0, 0, 0, 0);
    }
}

// ---------------- K1: final feature reduction ----------------
__global__ void k_feat2() {
    int d = threadIdx.x;  // 256
    float s = 0.f;
#pragma unroll 8
    for (int b = 0; b < FEAT_BLOCKS; b++) s += g_pfsum[b][d];
    g_fsum[d] = -2.f * s;
}

// ---------------- K2: cp.async pipelined scores ----------------
__device__ __forceinline__ uint32_t smem_u32(const void* p) {
    uint32_t a;
    asm("{ .reg .u64 t; cvta.to.shared.u64 t, %1; cvt.u32.u64 %0, t; }" : "=r"(a) : "l"(p));
    return a;
}

__device__ __forceinline__ void issue_tile(const float* __restrict__ mem,
                                           int tile, float* dst, int t) {
    const char* g = (const char*)mem + (size_t)tile * TILE_BYTES + t * 16;
    uint32_t sa = smem_u32(dst) + t * 16;
#pragma unroll
    for (int k = 0; k < 8; k++) {
        asm volatile("cp.async.cg.shared.global [%0], [%1], 16;"
                     :: "r"(sa + k * 4096), "l"(g + k * 4096));
    }
    asm volatile("cp.async.commit_group;");
}

__global__ void __launch_bounds__(256) k_scores(const float* __restrict__ mem, int NT) {
    extern __shared__ __align__(16) float smem[];
    float* buf[2] = { smem, smem + TROWS * D };
    float* sf = smem + 2 * TROWS * D;

    int t = threadIdx.x;
    sf[t] = g_fsum[t];                 // first loop barrier publishes this

    int warp = t >> 5, lane = t & 31;
    const float Bf = (float)BQ;

    int tile = blockIdx.x;
    if (tile >= NT) return;
    issue_tile(mem, tile, buf[0], t);

    int stage = 0;
    for (; tile < NT; tile += SCORE_BLOCKS) {
        int next = tile + SCORE_BLOCKS;
        if (next < NT) {
            issue_tile(mem, next, buf[stage ^ 1], t);
            asm volatile("cp.async.wait_group 1;");
        } else {
            asm volatile("cp.async.wait_group 0;");
        }
        __syncthreads();

        // compute: warp handles 4 rows of this 32-row tile
        const float4* f4 = (const float4*)sf;
        float4 fa = f4[lane * 2], fb = f4[lane * 2 + 1];
        float* rp = buf[stage] + warp * 4 * D;
        float acc[4];
#pragma unroll
        for (int r = 0; r < 4; r++) {
            const float4* m4 = (const float4*)(rp + r * D);
            float4 a = m4[lane * 2], b = m4[lane * 2 + 1];
            acc[r] = a.x * (Bf * a.x + fa.x)
                   + a.y * (Bf * a.y + fa.y)
                   + a.z * (Bf * a.z + fa.z)
                   + a.w * (Bf * a.w + fa.w)
                   + b.x * (Bf * b.x + fb.x)
                   + b.y * (Bf * b.y + fb.y)
                   + b.z * (Bf * b.z + fb.z)
                   + b.w * (Bf * b.w + fb.w);
        }
#pragma unroll
        for (int o = 16; o > 0; o >>= 1) {
#pragma unroll
            for (int r = 0; r < 4; r++)
                acc[r] += __shfl_xor_sync(0xffffffffu, acc[r], o);
        }
        if (lane < 4) {
            int row = tile * TROWS + warp * 4 + lane;
            float v = lane == 0 ? acc[0] : lane == 1 ? acc[1] : lane == 2 ? acc[2] : acc[3];
            float score = -v;
            unsigned u = __float_as_uint(score);
            u = (u & 0x80000000u) ? ~u : (u | 0x80000000u);
            unsigned long long key =
                ((unsigned long long)u << 32) | (unsigned)(~row);
            g_keys[row] = key;
            atomicAdd(&g_hist[u >> 12], 1);
        }
        __syncthreads();   // all reads done before buffer reuse
        stage ^= 1;
    }
}

// ---------------- K3: chunk sums, warp-per-chunk (MLP 8, no barriers) ----------------
__global__ void k_chunksum() {
    int w = threadIdx.x >> 5, lane = threadIdx.x & 31;
    int chunk = blockIdx.x * 8 + w;          // 128 blocks * 8 warps
    const int4* h4 = (const int4*)(g_hist + chunk * 1024);
    int s = 0;
#pragma unroll
    for (int j = 0; j < 8; j++) {
        int4 v = h4[lane + j * 32];
        s += v.x + v.y + v.z + v.w;
    }
#pragma unroll
    for (int o = 16; o > 0; o >>= 1)
        s += __shfl_down_sync(0xffffffffu, s, o);
    if (lane == 0) g_chunk[chunk] = s;
}

// Inclusive suffix-sum over 1024 values held one-per-thread (shfl, 2 levels).
__device__ __forceinline__ int suffix1024(int s, int t, int lane, int w, int* warpsum) {
    int v = s;
#pragma unroll
    for (int off = 1; off < 32; off <<= 1) {
        int u = __shfl_down_sync(0xffffffffu, v, off);
        if (lane + off < 32) v += u;
    }
    if (lane == 0) warpsum[w] = v;
    __syncthreads();
    if (t < 32) {
        int wv = warpsum[t];
#pragma unroll
        for (int off = 1; off < 32; off <<= 1) {
            int u = __shfl_down_sync(0xffffffffu, wv, off);
            if (t + off < 32) wv += u;
        }
        warpsum[t] = wv;
    }
    __syncthreads();
    return v + ((w < 31) ? warpsum[w + 1] : 0);
}

// ---------------- K4: threshold — all-parallel ----------------
__global__ void k_thresh() {
    __shared__ int ssuf[NCHUNK];
    __shared__ int warpsum[32];
    __shared__ int sC, sCum;
    int t = threadIdx.x;  // 1024
    int lane = t & 31, w = t >> 5;

    int suf = suffix1024(g_chunk[t], t, lane, w, warpsum);
    ssuf[t] = suf;
    __syncthreads();
    if (suf >= KTOP && (t == NCHUNK - 1 || ssuf[t + 1] < KTOP)) {
        sC = t;
        sCum = (t == NCHUNK - 1) ? 0 : ssuf[t + 1];
    }
    __syncthreads();
    int C = sC, cumAbove = sCum;
    __syncthreads();

    int suf2 = suffix1024(g_hist[C * 1024 + t], t, lane, w, warpsum);
    ssuf[t] = suf2;
    __syncthreads();
    if (cumAbove + suf2 >= KTOP &&
        (t == NCHUNK - 1 || cumAbove + ssuf[t + 1] < KTOP)) {
        g_Tbin = C * 1024 + t;
    }
}

// ---------------- K5: collect candidates ----------------
__global__ void k_collect(int M) {
    int i = blockIdx.x * blockDim.x + threadIdx.x;
    if (i >= M) return;
    unsigned long long key = g_keys[i];
    int bin = (int)(key >> 44);
    if (bin >= g_Tbin) {
        int p = atomicAdd(&g_ncand, 1);
        if (p < CAND_MAX) g_cand[p] = key;
    }
}

// ---------------- K6: exact rank by counting (keys unique) ----------------
__global__ void k_rank() {
    __shared__ unsigned long long sk[CAND_MAX];  // 32 KB
    int t = threadIdx.x;                          // 1024
    int n = g_ncand;
    if (n > CAND_MAX) n = CAND_MAX;
    int npad = (n + 3) & ~3;

    for (int j = t; j < n; j += 1024) sk[j] = g_cand[j];
    if (n + t < npad) sk[n + t] = 0ULL;
    __syncthreads();

    int i = blockIdx.x * 1024 + t;
    if (i < n) {
        unsigned long long me = sk[i];
        int cnt = 0;
        for (int j = 0; j < npad; j += 4) {
            cnt += (sk[j]     > me);
            cnt += (sk[j + 1] > me);
            cnt += (sk[j + 2] > me);
            cnt += (sk[j + 3] > me);
        }
        if (cnt < KTOP) g_topidx[cnt] = (int)(~(unsigned)me);
    }
}

// ---------------- K7: gather winning rows ----------------
__global__ void k_gather(const float* __restrict__ mem, float* __restrict__ out) {
    int r = blockIdx.x * 4 + (threadIdx.x >> 6);  // 4 rows per block
    int t = threadIdx.x & 63;
    int idx = g_topidx[r];
    const float4* src = (const float4*)(mem + (size_t)idx * D);
    float4* dst = (float4*)(out + (size_t)r * D);
    dst[t] = src[t];
}

extern "C" void kernel_launch(void* const* d_in, const int* in_sizes, int n_in,
                              void* d_out, int out_size) {
    const float* p0 = (const float*)d_in[0];
    const float* p1 = (const float*)d_in[1];
    const float* feat;
    const float* mem;
    int M;
    if (in_sizes[0] <= in_sizes[1]) { feat = p0; mem = p1; M = in_sizes[1] / D; }
    else                            { feat = p1; mem = p0; M = in_sizes[0] / D; }
    int NT = (M + TROWS - 1) / TROWS;   // 3125 for M=100000 (exact)

    static int smem_set = 0;
    if (!smem_set) {
        cudaFuncSetAttribute(k_scores, cudaFuncAttributeMaxDynamicSharedMemorySize,
                             SMEM_SCORES * 4);
        smem_set = 1;
    }

    k_init<<<FEAT_BLOCKS + NBINS / 1024, 256>>>(feat);
    k_feat2<<<1, 256>>>();
    k_scores<<<SCORE_BLOCKS, 256, SMEM_SCORES * 4>>>(mem, NT);
    k_chunksum<<<NCHUNK / 8, 256>>>();
    k_thresh<<<1, 1024>>>();
    k_collect<<<(M + 255) / 256, 256>>>(M);
    k_rank<<<CAND_MAX / 1024, 1024>>>();
    k_gather<<<KTOP / 4, 256>>>(mem, (float*)d_out);
}

// round 7
// speedup vs baseline: 1.1660x; 1.1660x over previous
#include <cuda_runtime.h>
#include <stdint.h>

#define D 256
#define BQ 1024
#define KTOP 1024
#define MMAX 100000
#define CAND_MAX 2048
#define FEAT_BLOCKS 128
#define NBINS (1 << 20)
#define NCHUNK 1024
#define GRID 444          // 3 per SM * 148 — co-resident by construction
#define TB 256
#define NBAR 7

typedef unsigned long long ull;

// ---------------- static device scratch ----------------
__device__ ull g_bar;                  // monotonic grid-barrier counter
__device__ float g_pfsum[FEAT_BLOCKS][D];
__device__ float g_fsum[D];
__device__ ull g_keys[MMAX];
__device__ int g_hist[NBINS];          // 4 MB
__device__ int g_chunk[NCHUNK];
__device__ int g_Tbin;
__device__ ull g_cand[CAND_MAX];
__device__ int g_ncand;
__device__ int g_topidx[KTOP];

// ---------------- grid barrier (replay-safe, monotonic epoch base) ----------------
__device__ __forceinline__ void gbar(int k, ull* sbase) {
    __threadfence();                 // release (gpu scope)
    __syncthreads();
    if (threadIdx.x == 0) {
        ull old = atomicAdd(&g_bar, 1ULL);
        if (k == 0) *sbase = old - (old % (ull)(GRID * NBAR));
        ull target = *sbase + (ull)(k + 1) * GRID;
        while (*(volatile ull*)&g_bar < target) __nanosleep(32);
    }
    __syncthreads();
    __threadfence();                 // acquire + L1D invalidate
}

// inclusive suffix-sum over 256 values (one per thread, 8 warps)
__device__ __forceinline__ int suffix256(int v, int t, int lane, int w, int* wsum) {
#pragma unroll
    for (int off = 1; off < 32; off <<= 1) {
        int u = __shfl_down_sync(0xffffffffu, v, off);
        if (lane + off < 32) v += u;
    }
    if (lane == 0) wsum[w] = v;
    __syncthreads();
    if (t < 8) {
        int wv = wsum[t];
#pragma unroll
        for (int off = 1; off < 8; off <<= 1) {
            int u = __shfl_down_sync(0x000000ffu, wv, off);
            if (t + off < 8) wv += u;
        }
        wsum[t] = wv;
    }
    __syncthreads();
    return v + ((w < 7) ? wsum[w + 1] : 0);
}

// ---------------- the mega kernel ----------------
__global__ void __launch_bounds__(TB, 3)
k_mega(const float* __restrict__ feat, const float* __restrict__ mem,
       float* __restrict__ out, int M) {
    __shared__ __align__(16) char s_buf[CAND_MAX * 8];  // 16 KB: sf (P2) / sk (P6)
    __shared__ ull sbase;
    __shared__ int s_ssuf[TB];
    __shared__ int s_wsum[8];
    __shared__ int s_found, s_C, s_cum, s_carry;

    int t = threadIdx.x, blk = blockIdx.x;
    int warp = t >> 5, lane = t & 31;

    // ---- P0: zero hist + ncand; feature partial sums (blocks 0..127) ----
    {
        int4 z = make_int4(0, 0, 0, 0);
        int4* h4 = (int4*)g_hist;
        for (int i = blk * TB + t; i < NBINS / 4; i += GRID * TB) h4[i] = z;
        if (blk == 0 && t == 0) g_ncand = 0;
        if (blk < FEAT_BLOCKS) {
            const int RPB = BQ / FEAT_BLOCKS;  // 8
            float s = 0.f;
            int base = blk * RPB * D + t;
#pragma unroll
            for (int r = 0; r < RPB; r++) s += feat[base + r * D];
            g_pfsum[blk][t] = s;
        }
    }
    gbar(0, &sbase);

    // ---- P1: final feature reduction — EXACT R4 k_feat2 numerics (block 0) ----
    if (blk == 0) {
        float s = 0.f;
#pragma unroll 8
        for (int b = 0; b < FEAT_BLOCKS; b++) s += g_pfsum[b][t];
        g_fsum[t] = -2.f * s;
    }
    gbar(1, &sbase);

    // ---- P2: scores + keys + 20-bit histogram — EXACT R4 register path ----
    {
        float* sf = (float*)s_buf;
        sf[t] = g_fsum[t];
        __syncthreads();

        const float4* f4 = (const float4*)sf;
        float4 fa = f4[lane * 2], fb = f4[lane * 2 + 1];
        const float Bf = (float)BQ;

        int gw = blk * 8 + warp;                   // 3552 warps
        for (int rb = gw * 4; rb < M; rb += GRID * 8 * 4) {
            float4 A[4], Bv[4];
#pragma unroll
            for (int r = 0; r < 4; r++) {
                int row = rb + r;
                if (row >= M) row = M - 1;         // safe duplicate; discarded below
                const float4* m4 = (const float4*)(mem + (size_t)row * D);
                A[r]  = m4[lane * 2];
                Bv[r] = m4[lane * 2 + 1];
            }
            float acc[4];
#pragma unroll
            for (int r = 0; r < 4; r++) {
                float4 a = A[r], b = Bv[r];
                acc[r] = a.x * (Bf * a.x + fa.x)
                       + a.y * (Bf * a.y + fa.y)
                       + a.z * (Bf * a.z + fa.z)
                       + a.w * (Bf * a.w + fa.w)
                       + b.x * (Bf * b.x + fb.x)
                       + b.y * (Bf * b.y + fb.y)
                       + b.z * (Bf * b.z + fb.z)
                       + b.w * (Bf * b.w + fb.w);
            }
#pragma unroll
            for (int o = 16; o > 0; o >>= 1) {
#pragma unroll
                for (int r = 0; r < 4; r++)
                    acc[r] += __shfl_xor_sync(0xffffffffu, acc[r], o);
            }
            if (lane < 4 && rb + lane < M) {
                int row = rb + lane;
                float v = lane == 0 ? acc[0] : lane == 1 ? acc[1]
                        : lane == 2 ? acc[2] : acc[3];
                float score = -v;
                unsigned u = __float_as_uint(score);
                u = (u & 0x80000000u) ? ~u : (u | 0x80000000u);
                g_keys[row] = ((ull)u << 32) | (unsigned)(~row);
                atomicAdd(&g_hist[u >> 12], 1);
            }
        }
        __syncthreads();   // sf reads done before any later s_buf reuse
    }
    gbar(2, &sbase);

    // ---- P3: chunk sums — warp-per-chunk, direct store (no atomics) ----
    {
        int gw = blk * 8 + warp;
        if (gw < NCHUNK) {
            const int4* p4 = (const int4*)(g_hist + gw * 1024);
            int s = 0;
#pragma unroll
            for (int j = 0; j < 8; j++) {
                int4 v = p4[lane + 32 * j];
                s += v.x + v.y + v.z + v.w;
            }
#pragma unroll
            for (int o = 16; o > 0; o >>= 1)
                s += __shfl_down_sync(0xffffffffu, s, o);
            if (lane == 0) g_chunk[gw] = s;
        }
    }
    gbar(3, &sbase);

    // ---- P4: threshold — strip-wise 1-bin-per-thread scans (block 0) ----
    if (blk == 0) {
        // level 1: 1024 chunks, 4 strips high->low
        if (t == 0) { s_found = 0; s_carry = 0; }
        __syncthreads();
        for (int p = 3; p >= 0; p--) {
            int suf = suffix256(g_chunk[p * 256 + t], t, lane, warp, s_wsum);
            s_ssuf[t] = suf;
            __syncthreads();
            int carry = s_carry;
            if (!s_found && carry + suf >= KTOP &&
                (t == TB - 1 || carry + s_ssuf[t + 1] < KTOP)) {
                s_C = p * 256 + t;                            // boundary chunk
                s_cum = carry + ((t == TB - 1) ? 0 : s_ssuf[t + 1]);
                s_found = 1;
            }
            __syncthreads();
            if (t == 0 && !s_found) s_carry = carry + s_ssuf[0];
            __syncthreads();
        }
        // level 2: 1024 bins of chunk C, 4 strips high->low
        int C = s_C;
        if (t == 0) { s_found = 0; s_carry = s_cum; }
        __syncthreads();
        for (int p = 3; p >= 0; p--) {
            int suf = suffix256(g_hist[C * 1024 + p * 256 + t], t, lane, warp, s_wsum);
            s_ssuf[t] = suf;
            __syncthreads();
            int carry = s_carry;
            if (!s_found && carry + suf >= KTOP &&
                (t == TB - 1 || carry + s_ssuf[t + 1] < KTOP)) {
                g_Tbin = C * 1024 + p * 256 + t;
                s_found = 1;
            }
            __syncthreads();
            if (t == 0 && !s_found) s_carry = carry + s_ssuf[0];
            __syncthreads();
        }
    }
    gbar(4, &sbase);

    // ---- P5: collect candidates ----
    {
        int Tb = g_Tbin;
        for (int i = blk * TB + t; i < M; i += GRID * TB) {
            ull key = g_keys[i];
            if ((int)(key >> 44) >= Tb) {
                int p = atomicAdd(&g_ncand, 1);
                if (p < CAND_MAX) g_cand[p] = key;
            }
        }
    }
    gbar(5, &sbase);

    // ---- P6: exact rank by counting (blocks 0..7; keys unique) ----
    if (blk < CAND_MAX / TB) {
        ull* sk = (ull*)s_buf;
        int n = g_ncand;
        if (n > CAND_MAX) n = CAND_MAX;
        int npad = (n + 3) & ~3;
        for (int j = t; j < npad; j += TB) sk[j] = (j < n) ? g_cand[j] : 0ULL;
        __syncthreads();
        int i = blk * TB + t;
        if (i < n) {
            ull me = sk[i];
            int cnt = 0;
            for (int j = 0; j < npad; j += 4) {
                cnt += (sk[j]     > me);
                cnt += (sk[j + 1] > me);
                cnt += (sk[j + 2] > me);
                cnt += (sk[j + 3] > me);
            }
            if (cnt < KTOP) g_topidx[cnt] = (int)(~(unsigned)me);
        }
    }
    gbar(6, &sbase);

    // ---- P7: gather winning rows ----
    for (int rr = blk * 4 + (t >> 6); rr < KTOP; rr += GRID * 4) {
        int idx = g_topidx[rr];
        const float4* src = (const float4*)(mem + (size_t)idx * D);
        float4* dst = (float4*)(out + (size_t)rr * D);
        dst[t & 63] = src[t & 63];
    }
}

extern "C" void kernel_launch(void* const* d_in, const int* in_sizes, int n_in,
                              void* d_out, int out_size) {
    const float* p0 = (const float*)d_in[0];
    const float* p1 = (const float*)d_in[1];
    const float* feat;
    const float* mem;
    int M;
    if (in_sizes[0] <= in_sizes[1]) { feat = p0; mem = p1; M = in_sizes[1] / D; }
    else                            { feat = p1; mem = p0; M = in_sizes[0] / D; }

    k_mega<<<GRID, TB>>>(feat, mem, (float*)d_out, M);
}

// round 8
// speedup vs baseline: 1.4662x; 1.2575x over previous
#include <cuda_runtime.h>
#include <stdint.h>

#define D 256
#define BQ 1024
#define KTOP 1024
#define MMAX 100000
#define CAND_MAX 4096
#define FEAT_BLOCKS 128
#define HBITS 13
#define HBINS (1 << HBITS)     // 8192 bins
#define GRID 592               // 4 per SM * 148 — co-resident by construction
#define TB 256
#define NBAR 6

typedef unsigned long long ull;

// ---------------- static device scratch ----------------
__device__ ull g_bar;                  // monotonic grid-barrier counter
__device__ float g_pfsum[FEAT_BLOCKS][D];
__device__ float g_fsum[D];
__device__ ull g_keys[MMAX];
__device__ int g_hist[HBINS];          // 32 KB
__device__ int g_Tbin;
__device__ ull g_cand[CAND_MAX];
__device__ int g_ncand;
__device__ int g_topidx[KTOP];

// ---------------- grid barrier (replay-safe, monotonic epoch base) ----------------
__device__ __forceinline__ void gbar(int k, ull* sbase) {
    __threadfence();                 // release (gpu scope)
    __syncthreads();
    if (threadIdx.x == 0) {
        ull old = atomicAdd(&g_bar, 1ULL);
        if (k == 0) *sbase = old - (old % (ull)(GRID * NBAR));
        ull target = *sbase + (ull)(k + 1) * GRID;
        while (*(volatile ull*)&g_bar < target) __nanosleep(32);
    }
    __syncthreads();
    __threadfence();                 // acquire + L1D invalidate
}

// inclusive suffix-sum over 256 values (one per thread, 8 warps)
__device__ __forceinline__ int suffix256(int v, int t, int lane, int w, int* wsum) {
#pragma unroll
    for (int off = 1; off < 32; off <<= 1) {
        int u = __shfl_down_sync(0xffffffffu, v, off);
        if (lane + off < 32) v += u;
    }
    if (lane == 0) wsum[w] = v;
    __syncthreads();
    if (t < 8) {
        int wv = wsum[t];
#pragma unroll
        for (int off = 1; off < 8; off <<= 1) {
            int u = __shfl_down_sync(0x000000ffu, wv, off);
            if (t + off < 8) wv += u;
        }
        wsum[t] = wv;
    }
    __syncthreads();
    return v + ((w < 7) ? wsum[w + 1] : 0);
}

// ---------------- the mega kernel ----------------
__global__ void __launch_bounds__(TB, 4)
k_mega(const float* __restrict__ feat, const float* __restrict__ mem,
       float* __restrict__ out, int M) {
    __shared__ __align__(16) char s_buf[CAND_MAX * 8];  // 32 KB: shist (P2) / sk (P5)
    __shared__ __align__(16) float sf[D];               // 1 KB: -2*fsum
    __shared__ ull sbase;
    __shared__ int s_ssuf[TB];
    __shared__ int s_wsum[8];

    int t = threadIdx.x, blk = blockIdx.x;
    int warp = t >> 5, lane = t & 31;

    // ---- P0: zero small globals; feature partial sums (blocks 0..127) ----
    {
        int i = blk * TB + t;
        if (i < HBINS) g_hist[i] = 0;      // blocks 0..31 cover 8192 bins
        if (i == 0) g_ncand = 0;
        if (blk < FEAT_BLOCKS) {
            const int RPB = BQ / FEAT_BLOCKS;  // 8
            float s = 0.f;
            int base = blk * RPB * D + t;
#pragma unroll
            for (int r = 0; r < RPB; r++) s += feat[base + r * D];
            g_pfsum[blk][t] = s;
        }
    }
    gbar(0, &sbase);

    // ---- P1: final feature reduction — EXACT R4/R7 numerics (block 0) ----
    if (blk == 0) {
        float s = 0.f;
#pragma unroll 8
        for (int b = 0; b < FEAT_BLOCKS; b++) s += g_pfsum[b][t];
        g_fsum[t] = -2.f * s;
    }
    gbar(1, &sbase);

    // ---- P2: scores + keys + smem 13-bit histogram, then merge ----
    {
        int* shist = (int*)s_buf;
        sf[t] = g_fsum[t];
#pragma unroll
        for (int i = t; i < HBINS; i += TB) shist[i] = 0;
        __syncthreads();

        const float4* f4 = (const float4*)sf;
        float4 fa = f4[lane * 2], fb = f4[lane * 2 + 1];
        const float Bf = (float)BQ;

        int gw = blk * 8 + warp;                    // 4736 warps
        for (int rb = gw * 4; rb < M; rb += GRID * 8 * 4) {
            float4 A[4], Bv[4];
#pragma unroll
            for (int r = 0; r < 4; r++) {
                int row = rb + r;
                if (row >= M) row = M - 1;          // safe duplicate; discarded below
                const float4* m4 = (const float4*)(mem + (size_t)row * D);
                A[r]  = m4[lane * 2];
                Bv[r] = m4[lane * 2 + 1];
            }
            float acc[4];
#pragma unroll
            for (int r = 0; r < 4; r++) {
                float4 a = A[r], b = Bv[r];
                acc[r] = a.x * (Bf * a.x + fa.x)
                       + a.y * (Bf * a.y + fa.y)
                       + a.z * (Bf * a.z + fa.z)
                       + a.w * (Bf * a.w + fa.w)
                       + b.x * (Bf * b.x + fb.x)
                       + b.y * (Bf * b.y + fb.y)
                       + b.z * (Bf * b.z + fb.z)
                       + b.w * (Bf * b.w + fb.w);
            }
#pragma unroll
            for (int o = 16; o > 0; o >>= 1) {
#pragma unroll
                for (int r = 0; r < 4; r++)
                    acc[r] += __shfl_xor_sync(0xffffffffu, acc[r], o);
            }
            if (lane < 4 && rb + lane < M) {
                int row = rb + lane;
                float v = lane == 0 ? acc[0] : lane == 1 ? acc[1]
                        : lane == 2 ? acc[2] : acc[3];
                float score = -v;
                unsigned u = __float_as_uint(score);
                u = (u & 0x80000000u) ? ~u : (u | 0x80000000u);
                g_keys[row] = ((ull)u << 32) | (unsigned)(~row);
                atomicAdd(&shist[u >> (32 - HBITS)], 1);
            }
        }
        __syncthreads();    // all block atomics into shist done
        for (int i = t; i < HBINS; i += TB) {
            int v = shist[i];
            if (v) atomicAdd(&g_hist[i], v);
        }
    }
    gbar(2, &sbase);

    // ---- P3: threshold — single pass, in-register refine (block 0) ----
    if (blk == 0) {
        int h[32];                      // bins [t*32, t*32+32)
        const int4* p4 = (const int4*)(g_hist + t * 32);
        int s = 0;
#pragma unroll
        for (int j = 0; j < 8; j++) {
            int4 v = p4[j];
            h[j * 4] = v.x; h[j * 4 + 1] = v.y; h[j * 4 + 2] = v.z; h[j * 4 + 3] = v.w;
            s += v.x + v.y + v.z + v.w;
        }
        int suf = suffix256(s, t, lane, warp, s_wsum);
        s_ssuf[t] = suf;
        __syncthreads();
        if (suf >= KTOP && (t == TB - 1 || s_ssuf[t + 1] < KTOP)) {
            int cum = (t == TB - 1) ? 0 : s_ssuf[t + 1];
#pragma unroll
            for (int j = 31; j >= 0; j--) {
                cum += h[j];
                if (cum >= KTOP) { g_Tbin = t * 32 + j; break; }
            }
        }
    }
    gbar(3, &sbase);

    // ---- P4: collect candidates ----
    {
        int Tb = g_Tbin;
        for (int i = blk * TB + t; i < M; i += GRID * TB) {
            ull key = g_keys[i];
            if ((int)(key >> (64 - HBITS)) >= Tb) {
                int p = atomicAdd(&g_ncand, 1);
                if (p < CAND_MAX) g_cand[p] = key;
            }
        }
    }
    gbar(4, &sbase);

    // ---- P5: exact rank by counting (blocks 0..15; keys unique) ----
    if (blk < CAND_MAX / TB) {
        ull* sk = (ull*)s_buf;
        int n = g_ncand;
        if (n > CAND_MAX) n = CAND_MAX;
        int npad = (n + 3) & ~3;
        for (int j = t; j < npad; j += TB) sk[j] = (j < n) ? g_cand[j] : 0ULL;
        __syncthreads();
        int i = blk * TB + t;
        if (i < n) {
            ull me = sk[i];
            int cnt = 0;
            for (int j = 0; j < npad; j += 4) {
                cnt += (sk[j]     > me);
                cnt += (sk[j + 1] > me);
                cnt += (sk[j + 2] > me);
                cnt += (sk[j + 3] > me);
            }
            if (cnt < KTOP) g_topidx[cnt] = (int)(~(unsigned)me);
        }
    }
    gbar(5, &sbase);

    // ---- P6: gather winning rows ----
    for (int rr = blk * 4 + (t >> 6); rr < KTOP; rr += GRID * 4) {
        int idx = g_topidx[rr];
        const float4* src = (const float4*)(mem + (size_t)idx * D);
        float4* dst = (float4*)(out + (size_t)rr * D);
        dst[t & 63] = src[t & 63];
    }
}

extern "C" void kernel_launch(void* const* d_in, const int* in_sizes, int n_in,
                              void* d_out, int out_size) {
    const float* p0 = (const float*)d_in[0];
    const float* p1 = (const float*)d_in[1];
    const float* feat;
    const float* mem;
    int M;
    if (in_sizes[0] <= in_sizes[1]) { feat = p0; mem = p1; M = in_sizes[1] / D; }
    else                            { feat = p1; mem = p0; M = in_sizes[0] / D; }

    k_mega<<<GRID, TB>>>(feat, mem, (float*)d_out, M);
}

// round 10
// speedup vs baseline: 1.5535x; 1.0595x over previous
#include <cuda_runtime.h>
#include <stdint.h>

#define D 256
#define BQ 1024
#define KTOP 1024
#define MMAX 100000
#define CAND_MAX 4096
#define FEAT_BLOCKS 128
#define HBITS 13
#define HBINS (1 << HBITS)     // 8192 bins
#define GRID 296               // 2 per SM * 148 — co-resident by regfile construction
#define TB 256
#define NBAR 6

typedef unsigned long long ull;

// ---------------- static device scratch ----------------
__device__ ull g_bar;                  // monotonic grid-barrier counter
__device__ float g_pfsum[FEAT_BLOCKS][D];
__device__ float g_fsum[D];
__device__ ull g_keys[MMAX];
__device__ int g_hist[HBINS];          // 32 KB
__device__ int g_Tbin;
__device__ ull g_cand[CAND_MAX];
__device__ int g_ncand;
__device__ int g_topidx[KTOP];

// ---------------- grid barrier (replay-safe, monotonic epoch base) ----------------
__device__ __forceinline__ void gbar(int k, ull* sbase) {
    __threadfence();                 // release (gpu scope)
    __syncthreads();
    if (threadIdx.x == 0) {
        ull old = atomicAdd(&g_bar, 1ULL);
        if (k == 0) *sbase = old - (old % (ull)(GRID * NBAR));
        ull target = *sbase + (ull)(k + 1) * GRID;
        while (*(volatile ull*)&g_bar < target) __nanosleep(32);
    }
    __syncthreads();
    __threadfence();                 // acquire + L1D invalidate
}

// packed f32x2 FMA (sm_103a FFMA2 — PTX-only)
__device__ __forceinline__ ull fma2(ull a, ull b, ull c) {
    ull d;
    asm("fma.rn.f32x2 %0, %1, %2, %3;" : "=l"(d) : "l"(a), "l"(b), "l"(c));
    return d;
}
__device__ __forceinline__ float unpack_add(ull v) {
    float lo, hi;
    asm("mov.b64 {%0, %1}, %2;" : "=f"(lo), "=f"(hi) : "l"(v));
    return lo + hi;
}

// inclusive suffix-sum over 256 values (one per thread, 8 warps)
__device__ __forceinline__ int suffix256(int v, int t, int lane, int w, int* wsum) {
#pragma unroll
    for (int off = 1; off < 32; off <<= 1) {
        int u = __shfl_down_sync(0xffffffffu, v, off);
        if (lane + off < 32) v += u;
    }
    if (lane == 0) wsum[w] = v;
    __syncthreads();
    if (t < 8) {
        int wv = wsum[t];
#pragma unroll
        for (int off = 1; off < 8; off <<= 1) {
            int u = __shfl_down_sync(0x000000ffu, wv, off);
            if (t + off < 8) wv += u;
        }
        wsum[t] = wv;
    }
    __syncthreads();
    return v + ((w < 7) ? wsum[w + 1] : 0);
}

// load 4 rows (2 ulonglong2 = 4 packed pairs per row per lane), clamped
__device__ __forceinline__ void load4(const float* __restrict__ mem, int rb, int M,
                                      int lane, ulonglong2* A) {
#pragma unroll
    for (int r = 0; r < 4; r++) {
        int row = rb + r;
        if (row >= M) row = M - 1;
        const ulonglong2* m2 = (const ulonglong2*)(mem + (size_t)row * D);
        A[r * 2]     = m2[lane * 2];
        A[r * 2 + 1] = m2[lane * 2 + 1];
    }
}

// ---------------- the mega kernel ----------------
__global__ void __launch_bounds__(TB, 2)
k_mega(const float* __restrict__ feat, const float* __restrict__ mem,
       float* __restrict__ out, int M) {
    __shared__ __align__(16) char s_buf[CAND_MAX * 8];  // 32 KB: shist (P2) / sk (P5)
    __shared__ __align__(16) float sf[D];               // 1 KB: -2*fsum
    __shared__ ull sbase;
    __shared__ int s_ssuf[TB];
    __shared__ int s_wsum[8];

    int t = threadIdx.x, blk = blockIdx.x;
    int warp = t >> 5, lane = t & 31;

    // ---- P0: zero hist + ncand; feature partial sums (blocks 0..127) ----
    {
        int i = blk * TB + t;
        if (i < HBINS) g_hist[i] = 0;
        if (i == 0) g_ncand = 0;
        if (blk < FEAT_BLOCKS) {
            const int RPB = BQ / FEAT_BLOCKS;  // 8
            float s = 0.f;
            int base = blk * RPB * D + t;
#pragma unroll
            for (int r = 0; r < RPB; r++) s += feat[base + r * D];
            g_pfsum[blk][t] = s;
        }
    }
    gbar(0, &sbase);

    // ---- P1: final feature reduction — EXACT R4/R7/R8 numerics (block 0) ----
    if (blk == 0) {
        float s = 0.f;
#pragma unroll 8
        for (int b = 0; b < FEAT_BLOCKS; b++) s += g_pfsum[b][t];
        g_fsum[t] = -2.f * s;
    }
    gbar(1, &sbase);

    // ---- P2: scores — software-pipelined, packed-f32x2 FMA ----
    {
        int* shist = (int*)s_buf;
        sf[t] = g_fsum[t];
#pragma unroll
        for (int i = t; i < HBINS; i += TB) shist[i] = 0;
        __syncthreads();

        const ulonglong2* f2p = (const ulonglong2*)sf;
        ulonglong2 fA = f2p[lane * 2], fB = f2p[lane * 2 + 1];
        const ull B2 = 0x4480000044800000ULL;  // (1024.f, 1024.f)

        const int STRIDE = GRID * 8 * 4;       // 9472
        int gw = blk * 8 + warp;
        int rb = gw * 4;
        if (rb < M) {
            ulonglong2 A[8];                   // current 4 rows
            load4(mem, rb, M, lane, A);
            while (rb < M) {
                int rb2 = rb + STRIDE;
                ulonglong2 C[8];               // prefetch next 4 rows
                if (rb2 < M) load4(mem, rb2, M, lane, C);

                float acc[4];
#pragma unroll
                for (int r = 0; r < 4; r++) {
                    ull a0 = A[r * 2].x, a1 = A[r * 2].y;
                    ull b0 = A[r * 2 + 1].x, b1 = A[r * 2 + 1].y;
                    ull s2 = fma2(a0, fma2(B2, a0, fA.x), 0ULL);
                    s2 = fma2(a1, fma2(B2, a1, fA.y), s2);
                    s2 = fma2(b0, fma2(B2, b0, fB.x), s2);
                    s2 = fma2(b1, fma2(B2, b1, fB.y), s2);
                    acc[r] = unpack_add(s2);
                }
#pragma unroll
                for (int o = 16; o > 0; o >>= 1) {
#pragma unroll
                    for (int r = 0; r < 4; r++)
                        acc[r] += __shfl_xor_sync(0xffffffffu, acc[r], o);
                }
                if (lane < 4 && rb + lane < M) {
                    int row = rb + lane;
                    float v = lane == 0 ? acc[0] : lane == 1 ? acc[1]
                            : lane == 2 ? acc[2] : acc[3];
                    float score = -v;
                    unsigned u = __float_as_uint(score);
                    u = (u & 0x80000000u) ? ~u : (u | 0x80000000u);
                    g_keys[row] = ((ull)u << 32) | (unsigned)(~row);
                    atomicAdd(&shist[u >> (32 - HBITS)], 1);
                }
#pragma unroll
                for (int j = 0; j < 8; j++) A[j] = C[j];
                rb = rb2;
            }
        }
        __syncthreads();    // all block atomics into shist done
        for (int i = t; i < HBINS; i += TB) {
            int v = shist[i];
            if (v) atomicAdd(&g_hist[i], v);
        }
    }
    gbar(2, &sbase);

    // ---- P3: threshold — single pass, in-register refine (block 0) ----
    if (blk == 0) {
        int h[32];                      // bins [t*32, t*32+32)
        const int4* p4 = (const int4*)(g_hist + t * 32);
        int s = 0;
#pragma unroll
        for (int j = 0; j < 8; j++) {
            int4 v = p4[j];
            h[j * 4] = v.x; h[j * 4 + 1] = v.y; h[j * 4 + 2] = v.z; h[j * 4 + 3] = v.w;
            s += v.x + v.y + v.z + v.w;
        }
        int suf = suffix256(s, t, lane, warp, s_wsum);
        s_ssuf[t] = suf;
        __syncthreads();
        if (suf >= KTOP && (t == TB - 1 || s_ssuf[t + 1] < KTOP)) {
            int cum = (t == TB - 1) ? 0 : s_ssuf[t + 1];
#pragma unroll
            for (int j = 31; j >= 0; j--) {
                cum += h[j];
                if (cum >= KTOP) { g_Tbin = t * 32 + j; break; }
            }
        }
    }
    gbar(3, &sbase);

    // ---- P4: collect candidates ----
    {
        int Tb = g_Tbin;
        for (int i = blk * TB + t; i < M; i += GRID * TB) {
            ull key = g_keys[i];
            if ((int)(key >> (64 - HBITS)) >= Tb) {
                int p = atomicAdd(&g_ncand, 1);
                if (p < CAND_MAX) g_cand[p] = key;
            }
        }
    }
    gbar(4, &sbase);

    // ---- P5: exact rank by counting (blocks 0..15; keys unique) ----
    if (blk < CAND_MAX / TB) {
        ull* sk = (ull*)s_buf;
        int n = g_ncand;
        if (n > CAND_MAX) n = CAND_MAX;
        int npad = (n + 3) & ~3;
        for (int j = t; j < npad; j += TB) sk[j] = (j < n) ? g_cand[j] : 0ULL;
        __syncthreads();
        int i = blk * TB + t;
        if (i < n) {
            ull me = sk[i];
            int cnt = 0;
            for (int j = 0; j < npad; j += 4) {
                cnt += (sk[j]     > me);
                cnt += (sk[j + 1] > me);
                cnt += (sk[j + 2] > me);
                cnt += (sk[j + 3] > me);
            }
            if (cnt < KTOP) g_topidx[cnt] = (int)(~(unsigned)me);
        }
    }
    gbar(5, &sbase);

    // ---- P6: gather winning rows ----
    for (int rr = blk * 4 + (t >> 6); rr < KTOP; rr += GRID * 4) {
        int idx = g_topidx[rr];
        const float4* src = (const float4*)(mem + (size_t)idx * D);
        float4* dst = (float4*)(out + (size_t)rr * D);
        dst[t & 63] = src[t & 63];
    }
}

extern "C" void kernel_launch(void* const* d_in, const int* in_sizes, int n_in,
                              void* d_out, int out_size) {
    const float* p0 = (const float*)d_in[0];
    const float* p1 = (const float*)d_in[1];
    const float* feat;
    const float* mem;
    int M;
    if (in_sizes[0] <= in_sizes[1]) { feat = p0; mem = p1; M = in_sizes[1] / D; }
    else                            { feat = p1; mem = p0; M = in_sizes[0] / D; }

    k_mega<<<GRID, TB>>>(feat, mem, (float*)d_out, M);
}

// round 12
// speedup vs baseline: 1.9873x; 1.2792x over previous
#include <cuda_runtime.h>
#include <stdint.h>

#define D 256
#define BQ 1024
#define KTOP 1024
#define MMAX 100000
#define CAND_MAX 4096
#define FEAT_BLOCKS 128
#define HBITS 13
#define HBINS (1 << HBITS)     // 8192 bins
#define GRID 444               // 3 per SM * 148 — co-resident by construction
#define TB 256
#define NBAR 6

typedef unsigned long long ull;

// ---------------- static device scratch ----------------
__device__ ull g_bar;                  // monotonic grid-barrier counter
__device__ float g_pfsum[FEAT_BLOCKS][D];
__device__ float g_fsum[D];
__device__ ull g_keys[MMAX];
__device__ int g_hist[HBINS];          // 32 KB
__device__ int g_Tbin;
__device__ ull g_cand[CAND_MAX];
__device__ int g_ncand;
__device__ int g_topidx[KTOP];

// ---------------- grid barrier (replay-safe, monotonic epoch base) ----------------
__device__ __forceinline__ void gbar(int k, ull* sbase) {
    __threadfence();                 // release (gpu scope)
    __syncthreads();
    if (threadIdx.x == 0) {
        ull old = atomicAdd(&g_bar, 1ULL);
        if (k == 0) *sbase = old - (old % (ull)(GRID * NBAR));
        ull target = *sbase + (ull)(k + 1) * GRID;
        while (*(volatile ull*)&g_bar < target) __nanosleep(32);
    }
    __syncthreads();
    __threadfence();                 // acquire + L1D invalidate
}

// packed f32x2 FMA (sm_103a FFMA2 — PTX-only)
__device__ __forceinline__ ull fma2(ull a, ull b, ull c) {
    ull d;
    asm("fma.rn.f32x2 %0, %1, %2, %3;" : "=l"(d) : "l"(a), "l"(b), "l"(c));
    return d;
}
__device__ __forceinline__ float unpack_add(ull v) {
    float lo, hi;
    asm("mov.b64 {%0, %1}, %2;" : "=f"(lo), "=f"(hi) : "l"(v));
    return lo + hi;
}

// inclusive suffix-sum over 256 values (one per thread, 8 warps)
__device__ __forceinline__ int suffix256(int v, int t, int lane, int w, int* wsum) {
#pragma unroll
    for (int off = 1; off < 32; off <<= 1) {
        int u = __shfl_down_sync(0xffffffffu, v, off);
        if (lane + off < 32) v += u;
    }
    if (lane == 0) wsum[w] = v;
    __syncthreads();
    if (t < 8) {
        int wv = wsum[t];
#pragma unroll
        for (int off = 1; off < 8; off <<= 1) {
            int u = __shfl_down_sync(0x000000ffu, wv, off);
            if (t + off < 8) wv += u;
        }
        wsum[t] = wv;
    }
    __syncthreads();
    return v + ((w < 7) ? wsum[w + 1] : 0);
}

// load 4 rows (2 ulonglong2 = 4 packed pairs per row per lane), clamped
__device__ __forceinline__ void load4(const float* __restrict__ mem, int rb, int M,
                                      int lane, ulonglong2* A) {
#pragma unroll
    for (int r = 0; r < 4; r++) {
        int row = rb + r;
        if (row >= M) row = M - 1;
        const ulonglong2* m2 = (const ulonglong2*)(mem + (size_t)row * D);
        A[r * 2]     = m2[lane * 2];
        A[r * 2 + 1] = m2[lane * 2 + 1];
    }
}

// ---------------- the mega kernel ----------------
__global__ void __launch_bounds__(TB, 3)
k_mega(const float* __restrict__ feat, const float* __restrict__ mem,
       float* __restrict__ out, int M) {
    __shared__ __align__(16) char s_buf[CAND_MAX * 8];  // 32 KB: shist (P2) / sk (P5)
    __shared__ __align__(16) float sf[D];               // 1 KB: -2*fsum
    __shared__ ull sbase;
    __shared__ int s_ssuf[TB];
    __shared__ int s_wsum[8];

    int t = threadIdx.x, blk = blockIdx.x;
    int warp = t >> 5, lane = t & 31;

    // ---- P0: zero hist + ncand; feature partial sums (blocks 0..127) ----
    {
        int i = blk * TB + t;
        if (i < HBINS) g_hist[i] = 0;
        if (i == 0) g_ncand = 0;
        if (blk < FEAT_BLOCKS) {
            const int RPB = BQ / FEAT_BLOCKS;  // 8
            float s = 0.f;
            int base = blk * RPB * D + t;
#pragma unroll
            for (int r = 0; r < RPB; r++) s += feat[base + r * D];
            g_pfsum[blk][t] = s;
        }
    }
    gbar(0, &sbase);

    // ---- P1: final feature reduction — same sequential order, deeper ILP ----
    if (blk == 0) {
        float s = 0.f;
#pragma unroll 16
        for (int b = 0; b < FEAT_BLOCKS; b++) s += g_pfsum[b][t];
        g_fsum[t] = -2.f * s;
    }
    gbar(1, &sbase);

    // ---- P2: scores — pipelined loads, packed FMA, 6-shfl reduction ----
    {
        int* shist = (int*)s_buf;
        sf[t] = g_fsum[t];
#pragma unroll
        for (int i = t; i < HBINS; i += TB) shist[i] = 0;
        __syncthreads();

        const ulonglong2* f2p = (const ulonglong2*)sf;
        ulonglong2 fA = f2p[lane * 2], fB = f2p[lane * 2 + 1];
        const ull B2 = 0x4480000044800000ULL;  // (1024.f, 1024.f)

        const int STRIDE = GRID * 8 * 4;       // 14208
        int gw = blk * 8 + warp;
        int rb = gw * 4;
        // winner-lane mapping for merged reduction: lanes {0,16,8,24} -> rows +{0,1,2,3}
        int wrow = (lane == 0) ? 0 : (lane == 16) ? 1 : (lane == 8) ? 2
                 : (lane == 24) ? 3 : -1;
        if (rb < M) {
            ulonglong2 A[8];                   // current 4 rows
            load4(mem, rb, M, lane, A);
            while (rb < M) {
                int rb2 = rb + STRIDE;
                ulonglong2 C[8];               // prefetch next 4 rows
                if (rb2 < M) load4(mem, rb2, M, lane, C);

                float acc[4];
#pragma unroll
                for (int r = 0; r < 4; r++) {
                    ull a0 = A[r * 2].x, a1 = A[r * 2].y;
                    ull b0 = A[r * 2 + 1].x, b1 = A[r * 2 + 1].y;
                    ull s2 = fma2(a0, fma2(B2, a0, fA.x), 0ULL);
                    s2 = fma2(a1, fma2(B2, a1, fA.y), s2);
                    s2 = fma2(b0, fma2(B2, b0, fB.x), s2);
                    s2 = fma2(b1, fma2(B2, b1, fB.y), s2);
                    acc[r] = unpack_add(s2);
                }
                // merged reduction: tree pairing identical to xor-16/8/4/2/1 butterfly
                bool hi16 = (lane & 16) != 0;
                float q0 = __shfl_xor_sync(0xffffffffu, hi16 ? acc[0] : acc[1], 16);
                float z  = (hi16 ? acc[1] : acc[0]) + q0;
                float q1 = __shfl_xor_sync(0xffffffffu, hi16 ? acc[2] : acc[3], 16);
                float w2 = (hi16 ? acc[3] : acc[2]) + q1;
                bool hi8 = (lane & 8) != 0;
                float q2 = __shfl_xor_sync(0xffffffffu, hi8 ? z : w2, 8);
                float v  = (hi8 ? w2 : z) + q2;
                v += __shfl_xor_sync(0xffffffffu, v, 4);
                v += __shfl_xor_sync(0xffffffffu, v, 2);
                v += __shfl_xor_sync(0xffffffffu, v, 1);

                if (wrow >= 0 && rb + wrow < M) {
                    int row = rb + wrow;
                    float score = -v;
                    unsigned u = __float_as_uint(score);
                    u = (u & 0x80000000u) ? ~u : (u | 0x80000000u);
                    g_keys[row] = ((ull)u << 32) | (unsigned)(~row);
                    atomicAdd(&shist[u >> (32 - HBITS)], 1);
                }
#pragma unroll
                for (int j = 0; j < 8; j++) A[j] = C[j];
                rb = rb2;
            }
        }
        __syncthreads();    // all block atomics into shist done
        for (int i = t; i < HBINS; i += TB) {
            int v = shist[i];
            if (v) atomicAdd(&g_hist[i], v);
        }
    }
    gbar(2, &sbase);

    // ---- P3: threshold — single pass, in-register refine (block 0) ----
    if (blk == 0) {
        int h[32];                      // bins [t*32, t*32+32)
        const int4* p4 = (const int4*)(g_hist + t * 32);
        int s = 0;
#pragma unroll
        for (int j = 0; j < 8; j++) {
            int4 v = p4[j];
            h[j * 4] = v.x; h[j * 4 + 1] = v.y; h[j * 4 + 2] = v.z; h[j * 4 + 3] = v.w;
            s += v.x + v.y + v.z + v.w;
        }
        int suf = suffix256(s, t, lane, warp, s_wsum);
        s_ssuf[t] = suf;
        __syncthreads();
        if (suf >= KTOP && (t == TB - 1 || s_ssuf[t + 1] < KTOP)) {
            int cum = (t == TB - 1) ? 0 : s_ssuf[t + 1];
#pragma unroll
            for (int j = 31; j >= 0; j--) {
                cum += h[j];
                if (cum >= KTOP) { g_Tbin = t * 32 + j; break; }
            }
        }
    }
    gbar(3, &sbase);

    // ---- P4: collect candidates ----
    {
        int Tb = g_Tbin;
        for (int i = blk * TB + t; i < M; i += GRID * TB) {
            ull key = g_keys[i];
            if ((int)(key >> (64 - HBITS)) >= Tb) {
                int p = atomicAdd(&g_ncand, 1);
                if (p < CAND_MAX) g_cand[p] = key;
            }
        }
    }
    gbar(4, &sbase);

    // ---- P5: exact rank — warp per candidate (keys unique) ----
    {
        ull* sk = (ull*)s_buf;
        int n = g_ncand;
        if (n > CAND_MAX) n = CAND_MAX;
        for (int j = t; j < n; j += TB) sk[j] = g_cand[j];
        __syncthreads();
        for (int c = blk * 8 + warp; c < n; c += GRID * 8) {
            ull me = sk[c];
            int cnt = 0;
            for (int j = lane; j < n; j += 32) cnt += (sk[j] > me);
#pragma unroll
            for (int o = 16; o > 0; o >>= 1)
                cnt += __shfl_down_sync(0xffffffffu, cnt, o);
            if (lane == 0 && cnt < KTOP) g_topidx[cnt] = (int)(~(unsigned)me);
        }
    }
    gbar(5, &sbase);

    // ---- P6: gather winning rows ----
    for (int rr = blk * 4 + (t >> 6); rr < KTOP; rr += GRID * 4) {
        int idx = g_topidx[rr];
        const float4* src = (const float4*)(mem + (size_t)idx * D);
        float4* dst = (float4*)(out + (size_t)rr * D);
        dst[t & 63] = src[t & 63];
    }
}

extern "C" void kernel_launch(void* const* d_in, const int* in_sizes, int n_in,
                              void* d_out, int out_size) {
    const float* p0 = (const float*)d_in[0];
    const float* p1 = (const float*)d_in[1];
    const float* feat;
    const float* mem;
    int M;
    if (in_sizes[0] <= in_sizes[1]) { feat = p0; mem = p1; M = in_sizes[1] / D; }
    else                            { feat = p1; mem = p0; M = in_sizes[0] / D; }

    k_mega<<<GRID, TB>>>(feat, mem, (float*)d_out, M);
}